// round 15
// baseline (speedup 1.0000x reference)
#include <cuda_runtime.h>
#include <cuda_fp16.h>
#include <cstdint>

#define N_NODES 100000
#define E_EDGES 3200000
#define F_IN_D  512
#define H_DIM   256
#define SCAN_BLKS ((N_NODES + 1023) / 1024)   // 98

// ---- scratch (device globals; no allocation allowed) ----
__device__ int    g_is64;
__device__ int    g_src [E_EDGES];
__device__ int    g_dst [E_EDGES];
__device__ int    g_degi[N_NODES];
__device__ int    g_off [N_NODES + 1];
__device__ int    g_cur [N_NODES];
__device__ int    g_incl[N_NODES];
__device__ int    g_bsum[SCAN_BLKS];
__device__ int    g_csr [E_EDGES];
__device__ float  g_dinv[N_NODES];
__device__ __align__(16) __half g_gbuf[(size_t)N_NODES * H_DIM];  // fp16: x@W1 (unscaled)
__device__ float  g_t   [N_NODES];

// ---- streams/events created at program load ----
static cudaStream_t s_side = 0;
static cudaEvent_t  ev_fork = 0, ev_join = 0;
static int s_ok = 0;
namespace {
struct StreamInit {
    StreamInit() {
        if (cudaStreamCreateWithFlags(&s_side, cudaStreamNonBlocking) == cudaSuccess &&
            cudaEventCreateWithFlags(&ev_fork, cudaEventDisableTiming) == cudaSuccess &&
            cudaEventCreateWithFlags(&ev_join, cudaEventDisableTiming) == cudaSuccess)
            s_ok = 1;
    }
} s_init;
}

// ---- fused: zero degree histogram + dtype probe ----
__global__ void k_zero_detect(const int* __restrict__ ei32) {
    int i = blockIdx.x * blockDim.x + threadIdx.x;
    if (i == 0) g_is64 = 1;
    if (i < N_NODES) g_degi[i] = 0;
    if (i < 4096) {
        if (ei32[2 * i + 1] != 0) g_is64 = 0;    // benign 1->0 race
    }
}

__global__ void k_prep(const void* __restrict__ ei) {
    int e = blockIdx.x * blockDim.x + threadIdx.x;
    if (e >= E_EDGES) return;
    int s, d;
    if (g_is64) {
        const long long* p = (const long long*)ei;
        s = (int)p[e];
        d = (int)p[E_EDGES + e];
    } else {
        const int* p = (const int*)ei;
        s = p[e];
        d = p[E_EDGES + e];
    }
    g_src[e] = s;
    g_dst[e] = d;
    atomicAdd(&g_degi[d], 1);
}

// ---- multi-block scan ----
__global__ __launch_bounds__(1024) void k_scan1() {
    __shared__ int wsum[32];
    const int tid = threadIdx.x, lane = tid & 31, wid = tid >> 5;
    int i = blockIdx.x * 1024 + tid;
    int v = (i < N_NODES) ? g_degi[i] : 0;
    int inc = v;
#pragma unroll
    for (int o = 1; o < 32; o <<= 1) {
        int t = __shfl_up_sync(0xffffffffu, inc, o);
        if (lane >= o) inc += t;
    }
    if (lane == 31) wsum[wid] = inc;
    __syncthreads();
    if (wid == 0) {
        int w = wsum[lane];
#pragma unroll
        for (int o = 1; o < 32; o <<= 1) {
            int t = __shfl_up_sync(0xffffffffu, w, o);
            if (lane >= o) w += t;
        }
        wsum[lane] = w;
    }
    __syncthreads();
    int wpre = (wid > 0) ? wsum[wid - 1] : 0;
    if (i < N_NODES) g_incl[i] = wpre + inc;
    if (tid == 1023) g_bsum[blockIdx.x] = wpre + inc;
}

__global__ __launch_bounds__(128) void k_scan2() {
    __shared__ int wsum[4];
    const int tid = threadIdx.x, lane = tid & 31, wid = tid >> 5;
    int v = (tid < SCAN_BLKS) ? g_bsum[tid] : 0;
    int inc = v;
#pragma unroll
    for (int o = 1; o < 32; o <<= 1) {
        int t = __shfl_up_sync(0xffffffffu, inc, o);
        if (lane >= o) inc += t;
    }
    if (lane == 31) wsum[wid] = inc;
    __syncthreads();
    int wpre = 0;
    for (int w = 0; w < wid; w++) wpre += wsum[w];
    if (tid < SCAN_BLKS) g_bsum[tid] = wpre + inc - v;
}

__global__ void k_scan3() {
    int i = blockIdx.x * blockDim.x + threadIdx.x;
    if (i >= N_NODES) return;
    int v    = g_degi[i];
    int incl = g_bsum[i >> 10] + g_incl[i];
    g_off[i + 1] = incl;
    g_cur[i]     = incl - v;
    g_dinv[i]    = rsqrtf((float)v + 1.0f);
    if (i == 0) g_off[0] = 0;
}

__global__ void k_fill_csr() {
    int e = blockIdx.x * blockDim.x + threadIdx.x;
    if (e >= E_EDGES) return;
    int slot = atomicAdd(&g_cur[g_dst[e]], 1);
    g_csr[slot] = g_src[e];
}

// ------- tf32 MMA GEMM1: 2-stage double buffer, ONE barrier per K-iter -------
// 71.7 KB smem -> 2 CTAs/SM (16 warps); single __syncthreads per iteration.
#define A_PITCH 36
#define B_PITCH 136
#define A_STG  (128 * A_PITCH)
#define B_STG  (32 * B_PITCH)
#define GEMM_SMEM_BYTES ((2 * A_STG + 2 * B_STG) * 4)

__device__ __forceinline__ void cp16(uint32_t smem_addr, const void* gsrc, int src_bytes) {
    asm volatile("cp.async.cg.shared.global [%0], [%1], 16, %2;"
                 :: "r"(smem_addr), "l"(gsrc), "r"(src_bytes));
}

__global__ __launch_bounds__(256) void k_gemm1(const float* __restrict__ x,
                                               const float* __restrict__ W1) {
    extern __shared__ float smem[];
    float* As = smem;                 // [2][A_STG]
    float* Bs = smem + 2 * A_STG;     // [2][B_STG]

    const int tid  = threadIdx.x;
    const int lane = tid & 31;
    const int warp = tid >> 5;
    const int wm   = warp & 3;
    const int wn   = warp >> 2;
    const int g    = lane >> 2;
    const int qc   = lane & 3;
    const int bm0  = blockIdx.x * 128;
    const int bn0  = blockIdx.y * 128;

    const uint32_t as_u32 = (uint32_t)__cvta_generic_to_shared(As);
    const uint32_t bs_u32 = (uint32_t)__cvta_generic_to_shared(Bs);

    float acc[2][8][4];
#pragma unroll
    for (int mt = 0; mt < 2; mt++)
#pragma unroll
        for (int nt = 0; nt < 8; nt++)
#pragma unroll
            for (int i = 0; i < 4; i++) acc[mt][nt][i] = 0.0f;

    auto load_tiles = [&](int k0, int buf) {
#pragma unroll
        for (int i = 0; i < 4; i++) {
            int idx = tid + i * 256;
            int row = idx >> 3;
            int col = (idx & 7) * 4;
            int grow = bm0 + row;
            int ok = (grow < N_NODES);
            const float* src = &x[(size_t)(ok ? grow : 0) * F_IN_D + k0 + col];
            cp16(as_u32 + (buf * A_STG + row * A_PITCH + col) * 4, src, ok ? 16 : 0);
        }
#pragma unroll
        for (int i = 0; i < 4; i++) {
            int idx = tid + i * 256;
            int row = idx >> 5;
            int col = (idx & 31) * 4;
            cp16(bs_u32 + (buf * B_STG + row * B_PITCH + col) * 4,
                 &W1[(size_t)(k0 + row) * H_DIM + bn0 + col], 16);
        }
        asm volatile("cp.async.commit_group;");
    };

    load_tiles(0, 0);

    for (int k0 = 0, it = 0; k0 < F_IN_D; k0 += 32, it++) {
        int buf = it & 1;
        asm volatile("cp.async.wait_group 0;");   // current buf's load complete
        __syncthreads();                          // all warps done reading buf^1

        // prefetch next chunk into buf^1 (safe: everyone passed the barrier)
        if (k0 + 32 < F_IN_D) load_tiles(k0 + 32, buf ^ 1);

        const float* A = As + buf * A_STG;
        const float* B = Bs + buf * B_STG;
#pragma unroll
        for (int kk = 0; kk < 32; kk += 8) {
            uint32_t a[2][4];
#pragma unroll
            for (int mt = 0; mt < 2; mt++) {
                int r0 = wm * 32 + mt * 16 + g;
                const float* pa = &A[r0 * A_PITCH + kk + qc];
                a[mt][0] = __float_as_uint(pa[0]);
                a[mt][1] = __float_as_uint(pa[8 * A_PITCH]);
                a[mt][2] = __float_as_uint(pa[4]);
                a[mt][3] = __float_as_uint(pa[8 * A_PITCH + 4]);
            }
#pragma unroll
            for (int nt = 0; nt < 8; nt++) {
                int c0 = wn * 64 + nt * 8 + g;
                uint32_t b0 = __float_as_uint(B[(kk + qc) * B_PITCH + c0]);
                uint32_t b1 = __float_as_uint(B[(kk + qc + 4) * B_PITCH + c0]);
#pragma unroll
                for (int mt = 0; mt < 2; mt++) {
                    asm volatile(
                        "mma.sync.aligned.m16n8k8.row.col.f32.tf32.tf32.f32 "
                        "{%0,%1,%2,%3}, {%4,%5,%6,%7}, {%8,%9}, {%0,%1,%2,%3};"
                        : "+f"(acc[mt][nt][0]), "+f"(acc[mt][nt][1]),
                          "+f"(acc[mt][nt][2]), "+f"(acc[mt][nt][3])
                        : "r"(a[mt][0]), "r"(a[mt][1]), "r"(a[mt][2]), "r"(a[mt][3]),
                          "r"(b0), "r"(b1));
                }
            }
        }
    }

    // epilogue: store raw h as fp16 (dinv applied in k_fuse)
#pragma unroll
    for (int mt = 0; mt < 2; mt++) {
        int row0 = bm0 + wm * 32 + mt * 16 + g;
        int row1 = row0 + 8;
#pragma unroll
        for (int nt = 0; nt < 8; nt++) {
            int col = bn0 + wn * 64 + nt * 8 + qc * 2;
            if (row0 < N_NODES)
                *(__half2*)&g_gbuf[(size_t)row0 * H_DIM + col] =
                    __floats2half2_rn(acc[mt][nt][0], acc[mt][nt][1]);
            if (row1 < N_NODES)
                *(__half2*)&g_gbuf[(size_t)row1 * H_DIM + col] =
                    __floats2half2_rn(acc[mt][nt][2], acc[mt][nt][3]);
        }
    }
}

// ---- fused layer-1 aggregation + ReLU + layer-2 matvec: one warp per node ----
__global__ __launch_bounds__(256) void k_fuse(const float* __restrict__ b1,
                                              const float* __restrict__ W2) {
    int gw   = (blockIdx.x * blockDim.x + threadIdx.x) >> 5;
    int lane = threadIdx.x & 31;
    if (gw >= N_NODES) return;

    float a[8];
#pragma unroll
    for (int i = 0; i < 8; i++) a[i] = 0.0f;

    auto add_row = [&](uint4 v, float sc) {
        const __half2* h = (const __half2*)&v;
#pragma unroll
        for (int i = 0; i < 4; i++) {
            float2 f = __half22float2(h[i]);
            a[2 * i]     = fmaf(sc, f.x, a[2 * i]);
            a[2 * i + 1] = fmaf(sc, f.y, a[2 * i + 1]);
        }
    };

    const float dv = g_dinv[gw];
    add_row(((const uint4*)(g_gbuf + (size_t)gw * H_DIM))[lane], dv);

    const int beg = g_off[gw];
    const int end = g_off[gw + 1];
    for (int j = beg; j < end; ++j) {
        int src = g_csr[j];
        add_row(((const uint4*)(g_gbuf + (size_t)src * H_DIM))[lane], g_dinv[src]);
    }

    int c = lane * 8;
    float4 bb0 = *(const float4*)&b1[c];
    float4 bb1 = *(const float4*)&b1[c + 4];
    float4 w0  = *(const float4*)&W2[c];
    float4 w1  = *(const float4*)&W2[c + 4];

    float s = 0.0f;
    s += fmaxf(fmaf(dv, a[0], bb0.x), 0.f) * w0.x;
    s += fmaxf(fmaf(dv, a[1], bb0.y), 0.f) * w0.y;
    s += fmaxf(fmaf(dv, a[2], bb0.z), 0.f) * w0.z;
    s += fmaxf(fmaf(dv, a[3], bb0.w), 0.f) * w0.w;
    s += fmaxf(fmaf(dv, a[4], bb1.x), 0.f) * w1.x;
    s += fmaxf(fmaf(dv, a[5], bb1.y), 0.f) * w1.y;
    s += fmaxf(fmaf(dv, a[6], bb1.z), 0.f) * w1.z;
    s += fmaxf(fmaf(dv, a[7], bb1.w), 0.f) * w1.w;

#pragma unroll
    for (int o = 16; o > 0; o >>= 1) s += __shfl_down_sync(0xffffffffu, s, o);
    if (lane == 0) g_t[gw] = dv * s;
}

// ---- layer-2 aggregation ----
__global__ __launch_bounds__(256) void k_agg2(const float* __restrict__ b2,
                                              float* __restrict__ out) {
    int gw   = (blockIdx.x * blockDim.x + threadIdx.x) >> 5;
    int lane = threadIdx.x & 31;
    if (gw >= N_NODES) return;
    const int beg = g_off[gw];
    const int end = g_off[gw + 1];
    float s = (lane == 0) ? g_t[gw] : 0.0f;
    for (int j = beg + lane; j < end; j += 32) s += g_t[g_csr[j]];
#pragma unroll
    for (int o = 16; o > 0; o >>= 1) s += __shfl_down_sync(0xffffffffu, s, o);
    if (lane == 0) out[gw] = fmaf(g_dinv[gw], s, b2[0]);
}

// ---------------- launch ----------------
extern "C" void kernel_launch(void* const* d_in, const int* in_sizes, int n_in,
                              void* d_out, int out_size) {
    const float* x   = (const float*)d_in[0];
    const void*  ei  = d_in[1];
    const float* W1  = (const float*)d_in[2];
    const float* b1  = (const float*)d_in[3];
    const float* W2  = (const float*)d_in[4];
    const float* b2  = (const float*)d_in[5];
    float*       out = (float*)d_out;

    (void)in_sizes; (void)n_in; (void)out_size;

    static int attr_set = 0;
    if (!attr_set) {
        cudaFuncSetAttribute(k_gemm1, cudaFuncAttributeMaxDynamicSharedMemorySize,
                             GEMM_SMEM_BYTES);
        attr_set = 1;
    }

    const int TB = 256;
    const int nb_nodes = (N_NODES + TB - 1) / TB;
    const int nb_edges = (E_EDGES + TB - 1) / TB;
    const int warps_blocks = (N_NODES * 32 + TB - 1) / TB;
    dim3 ggrid((N_NODES + 127) / 128, H_DIM / 128);

    if (s_ok) {
        // GEMM forked at stream head — starts immediately, chain overlaps it.
        cudaEventRecord(ev_fork, 0);
        cudaStreamWaitEvent(s_side, ev_fork, 0);
        k_gemm1<<<ggrid, 256, GEMM_SMEM_BYTES, s_side>>>(x, W1);
        cudaEventRecord(ev_join, s_side);

        k_zero_detect<<<nb_nodes, TB>>>((const int*)ei);
        k_prep<<<nb_edges, TB>>>(ei);
        k_scan1<<<SCAN_BLKS, 1024>>>();
        k_scan2<<<1, 128>>>();
        k_scan3<<<nb_nodes, TB>>>();
        k_fill_csr<<<nb_edges, TB>>>();

        cudaStreamWaitEvent(0, ev_join, 0);
    } else {
        k_zero_detect<<<nb_nodes, TB>>>((const int*)ei);
        k_prep<<<nb_edges, TB>>>(ei);
        k_scan1<<<SCAN_BLKS, 1024>>>();
        k_scan2<<<1, 128>>>();
        k_scan3<<<nb_nodes, TB>>>();
        k_fill_csr<<<nb_edges, TB>>>();
        k_gemm1<<<ggrid, 256, GEMM_SMEM_BYTES>>>(x, W1);
    }

    k_fuse<<<warps_blocks, TB>>>(b1, W2);
    k_agg2<<<warps_blocks, TB>>>(b2, out);
}

// round 16
// speedup vs baseline: 1.0724x; 1.0724x over previous
#include <cuda_runtime.h>
#include <cuda_fp16.h>
#include <cstdint>

#define N_NODES 100000
#define E_EDGES 3200000
#define F_IN_D  512
#define H_DIM   256
#define SCAN_BLKS ((N_NODES + 1023) / 1024)   // 98

// ---- scratch (device globals; no allocation allowed) ----
__device__ int    g_is64;
__device__ int    g_src [E_EDGES];
__device__ int    g_dst [E_EDGES];
__device__ int    g_degi[N_NODES];
__device__ int    g_off [N_NODES + 1];
__device__ int    g_cur [N_NODES];
__device__ int    g_incl[N_NODES];
__device__ int    g_bsum[SCAN_BLKS];
__device__ int    g_csr [E_EDGES];
__device__ float  g_dinv[N_NODES];
__device__ __align__(16) __half g_xh [(size_t)N_NODES * F_IN_D];  // fp16 copy of x
__device__ __align__(16) __half g_w1h[(size_t)H_DIM * F_IN_D];    // fp16 W1^T [n][k]
__device__ __align__(16) __half g_gbuf[(size_t)N_NODES * H_DIM];  // fp16: x@W1 (unscaled)
__device__ float  g_t   [N_NODES];

// ---- streams/events created at program load ----
static cudaStream_t s_side = 0;
static cudaEvent_t  ev_fork = 0, ev_join = 0;
static int s_ok = 0;
namespace {
struct StreamInit {
    StreamInit() {
        if (cudaStreamCreateWithFlags(&s_side, cudaStreamNonBlocking) == cudaSuccess &&
            cudaEventCreateWithFlags(&ev_fork, cudaEventDisableTiming) == cudaSuccess &&
            cudaEventCreateWithFlags(&ev_join, cudaEventDisableTiming) == cudaSuccess)
            s_ok = 1;
    }
} s_init;
}

// ---- fused: zero degree histogram + dtype probe ----
__global__ void k_zero_detect(const int* __restrict__ ei32) {
    int i = blockIdx.x * blockDim.x + threadIdx.x;
    if (i == 0) g_is64 = 1;
    if (i < N_NODES) g_degi[i] = 0;
    if (i < 4096) {
        if (ei32[2 * i + 1] != 0) g_is64 = 0;    // benign 1->0 race
    }
}

__global__ void k_prep(const void* __restrict__ ei) {
    int e = blockIdx.x * blockDim.x + threadIdx.x;
    if (e >= E_EDGES) return;
    int s, d;
    if (g_is64) {
        const long long* p = (const long long*)ei;
        s = (int)p[e];
        d = (int)p[E_EDGES + e];
    } else {
        const int* p = (const int*)ei;
        s = p[e];
        d = p[E_EDGES + e];
    }
    g_src[e] = s;
    g_dst[e] = d;
    atomicAdd(&g_degi[d], 1);
}

// ---- multi-block scan ----
__global__ __launch_bounds__(1024) void k_scan1() {
    __shared__ int wsum[32];
    const int tid = threadIdx.x, lane = tid & 31, wid = tid >> 5;
    int i = blockIdx.x * 1024 + tid;
    int v = (i < N_NODES) ? g_degi[i] : 0;
    int inc = v;
#pragma unroll
    for (int o = 1; o < 32; o <<= 1) {
        int t = __shfl_up_sync(0xffffffffu, inc, o);
        if (lane >= o) inc += t;
    }
    if (lane == 31) wsum[wid] = inc;
    __syncthreads();
    if (wid == 0) {
        int w = wsum[lane];
#pragma unroll
        for (int o = 1; o < 32; o <<= 1) {
            int t = __shfl_up_sync(0xffffffffu, w, o);
            if (lane >= o) w += t;
        }
        wsum[lane] = w;
    }
    __syncthreads();
    int wpre = (wid > 0) ? wsum[wid - 1] : 0;
    if (i < N_NODES) g_incl[i] = wpre + inc;
    if (tid == 1023) g_bsum[blockIdx.x] = wpre + inc;
}

__global__ __launch_bounds__(128) void k_scan2() {
    __shared__ int wsum[4];
    const int tid = threadIdx.x, lane = tid & 31, wid = tid >> 5;
    int v = (tid < SCAN_BLKS) ? g_bsum[tid] : 0;
    int inc = v;
#pragma unroll
    for (int o = 1; o < 32; o <<= 1) {
        int t = __shfl_up_sync(0xffffffffu, inc, o);
        if (lane >= o) inc += t;
    }
    if (lane == 31) wsum[wid] = inc;
    __syncthreads();
    int wpre = 0;
    for (int w = 0; w < wid; w++) wpre += wsum[w];
    if (tid < SCAN_BLKS) g_bsum[tid] = wpre + inc - v;
}

__global__ void k_scan3() {
    int i = blockIdx.x * blockDim.x + threadIdx.x;
    if (i >= N_NODES) return;
    int v    = g_degi[i];
    int incl = g_bsum[i >> 10] + g_incl[i];
    g_off[i + 1] = incl;
    g_cur[i]     = incl - v;
    g_dinv[i]    = rsqrtf((float)v + 1.0f);
    if (i == 0) g_off[0] = 0;
}

__global__ void k_fill_csr() {
    int e = blockIdx.x * blockDim.x + threadIdx.x;
    if (e >= E_EDGES) return;
    int slot = atomicAdd(&g_cur[g_dst[e]], 1);
    g_csr[slot] = g_src[e];
}

// ---- convert x to fp16 (8 elems/thread) ----
__global__ __launch_bounds__(256) void k_xh(const float* __restrict__ x) {
    size_t i = ((size_t)blockIdx.x * blockDim.x + threadIdx.x) * 8;
    float4 v0 = *(const float4*)&x[i];
    float4 v1 = *(const float4*)&x[i + 4];
    __half2 h[4];
    h[0] = __floats2half2_rn(v0.x, v0.y);
    h[1] = __floats2half2_rn(v0.z, v0.w);
    h[2] = __floats2half2_rn(v1.x, v1.y);
    h[3] = __floats2half2_rn(v1.z, v1.w);
    *(uint4*)&g_xh[i] = *(uint4*)h;
}

// ---- W1 [k][n] f32 -> g_w1h [n][k] fp16 ----
__global__ __launch_bounds__(1024) void k_wh(const float* __restrict__ W1) {
    __shared__ float tile[32][33];
    int k0 = blockIdx.x * 32;
    int n0 = blockIdx.y * 32;
    int tx = threadIdx.x & 31;
    int ty = threadIdx.x >> 5;
    tile[ty][tx] = W1[(size_t)(k0 + ty) * H_DIM + n0 + tx];
    __syncthreads();
    g_w1h[(size_t)(n0 + ty) * F_IN_D + k0 + tx] = __float2half_rn(tile[tx][ty]);
}

// ------- fp16 MMA GEMM1 (m16n8k16), 3-stage cp.async, 128x128 tile -------
// A smem [128 m][40 halves] (32 data + 8 pad), B smem [128 n][40 halves].
// pitch 40 halves = 20 words: (g*20+qc) mod 32 all-distinct -> bank-clean.
#define AH_PITCH 40
#define AH_STG   (128 * AH_PITCH)           // halves per A stage (5120)
#define BH_STG   (128 * AH_PITCH)           // halves per B stage
#define N_STAGE  3
#define GEMM_SMEM_BYTES (N_STAGE * (AH_STG + BH_STG) * 2)   // 61440 B

__device__ __forceinline__ void cp16(uint32_t smem_addr, const void* gsrc, int src_bytes) {
    asm volatile("cp.async.cg.shared.global [%0], [%1], 16, %2;"
                 :: "r"(smem_addr), "l"(gsrc), "r"(src_bytes));
}

__global__ __launch_bounds__(256) void k_gemm1() {
    extern __shared__ __half smem[];
    __half* As = smem;                       // [N_STAGE][AH_STG]
    __half* Bs = smem + N_STAGE * AH_STG;    // [N_STAGE][BH_STG]

    const int tid  = threadIdx.x;
    const int lane = tid & 31;
    const int warp = tid >> 5;
    const int wm   = warp & 3;
    const int wn   = warp >> 2;
    const int g    = lane >> 2;
    const int qc   = lane & 3;
    const int bm0  = blockIdx.x * 128;
    const int bn0  = blockIdx.y * 128;

    const uint32_t as_u32 = (uint32_t)__cvta_generic_to_shared(As);
    const uint32_t bs_u32 = (uint32_t)__cvta_generic_to_shared(Bs);

    float acc[2][8][4];
#pragma unroll
    for (int mt = 0; mt < 2; mt++)
#pragma unroll
        for (int nt = 0; nt < 8; nt++)
#pragma unroll
            for (int i = 0; i < 4; i++) acc[mt][nt][i] = 0.0f;

    // each stage: A 128 rows x 64B (4 cp16/row -> 512) + B same -> 4 cp16/thread
    auto load_tiles = [&](int chunk, int buf) {
        int k0 = chunk * 32;
#pragma unroll
        for (int i = 0; i < 2; i++) {
            int idx = tid + i * 256;          // 0..511
            int row = idx >> 2;               // 0..127
            int seg = (idx & 3) * 8;          // half offset in row (0,8,16,24)
            int grow = bm0 + row;
            int ok = (grow < N_NODES);
            const __half* src = &g_xh[(size_t)(ok ? grow : 0) * F_IN_D + k0 + seg];
            cp16(as_u32 + (buf * AH_STG + row * AH_PITCH + seg) * 2, src, ok ? 16 : 0);
        }
#pragma unroll
        for (int i = 0; i < 2; i++) {
            int idx = tid + i * 256;
            int row = idx >> 2;               // n index 0..127
            int seg = (idx & 3) * 8;
            cp16(bs_u32 + (buf * BH_STG + row * AH_PITCH + seg) * 2,
                 &g_w1h[(size_t)(bn0 + row) * F_IN_D + k0 + seg], 16);
        }
        asm volatile("cp.async.commit_group;");
    };

    load_tiles(0, 0);
    load_tiles(1, 1);

    const int NCH = F_IN_D / 32;  // 16
    for (int it = 0; it < NCH; it++) {
        int s = it % N_STAGE;
        if (it + 1 < NCH)
            asm volatile("cp.async.wait_group 1;");
        else
            asm volatile("cp.async.wait_group 0;");
        __syncthreads();

        const uint32_t* A = (const uint32_t*)(As + s * AH_STG);
        const uint32_t* B = (const uint32_t*)(Bs + s * BH_STG);
#pragma unroll
        for (int ks = 0; ks < 2; ks++) {      // two k16 steps per 32-chunk
            int kk2 = ks * 8;                 // word offset within row (20-word pitch)
            uint32_t a[2][4];
#pragma unroll
            for (int mt = 0; mt < 2; mt++) {
                int r0 = wm * 32 + mt * 16 + g;
                const uint32_t* pa = &A[r0 * 20 + kk2 + qc];
                a[mt][0] = pa[0];             // {A[r0][2qc], +1}
                a[mt][1] = pa[8 * 20];        // {A[r0+8][2qc], +1}
                a[mt][2] = pa[4];             // {A[r0][2qc+8], +1}
                a[mt][3] = pa[8 * 20 + 4];    // {A[r0+8][2qc+8], +1}
            }
#pragma unroll
            for (int nt = 0; nt < 8; nt++) {
                int c0 = wn * 64 + nt * 8 + g;
                const uint32_t* pb = &B[c0 * 20 + kk2 + qc];
                uint32_t b0 = pb[0];          // {B[2qc][c0], B[2qc+1][c0]}
                uint32_t b1 = pb[4];          // {B[2qc+8][c0], +1}
#pragma unroll
                for (int mt = 0; mt < 2; mt++) {
                    asm volatile(
                        "mma.sync.aligned.m16n8k16.row.col.f32.f16.f16.f32 "
                        "{%0,%1,%2,%3}, {%4,%5,%6,%7}, {%8,%9}, {%0,%1,%2,%3};"
                        : "+f"(acc[mt][nt][0]), "+f"(acc[mt][nt][1]),
                          "+f"(acc[mt][nt][2]), "+f"(acc[mt][nt][3])
                        : "r"(a[mt][0]), "r"(a[mt][1]), "r"(a[mt][2]), "r"(a[mt][3]),
                          "r"(b0), "r"(b1));
                }
            }
        }
        // prefetch chunk it+2 into stage (it+2)%3 (its readers passed the barrier)
        if (it + 2 < NCH) load_tiles(it + 2, (it + 2) % N_STAGE);
    }

    // epilogue: store raw h as fp16 (dinv applied in k_fuse)
#pragma unroll
    for (int mt = 0; mt < 2; mt++) {
        int row0 = bm0 + wm * 32 + mt * 16 + g;
        int row1 = row0 + 8;
#pragma unroll
        for (int nt = 0; nt < 8; nt++) {
            int col = bn0 + wn * 64 + nt * 8 + qc * 2;
            if (row0 < N_NODES)
                *(__half2*)&g_gbuf[(size_t)row0 * H_DIM + col] =
                    __floats2half2_rn(acc[mt][nt][0], acc[mt][nt][1]);
            if (row1 < N_NODES)
                *(__half2*)&g_gbuf[(size_t)row1 * H_DIM + col] =
                    __floats2half2_rn(acc[mt][nt][2], acc[mt][nt][3]);
        }
    }
}

// ---- fused layer-1 aggregation + ReLU + layer-2 matvec: one warp per node ----
__global__ __launch_bounds__(256) void k_fuse(const float* __restrict__ b1,
                                              const float* __restrict__ W2) {
    int gw   = (blockIdx.x * blockDim.x + threadIdx.x) >> 5;
    int lane = threadIdx.x & 31;
    if (gw >= N_NODES) return;

    float a[8];
#pragma unroll
    for (int i = 0; i < 8; i++) a[i] = 0.0f;

    auto add_row = [&](uint4 v, float sc) {
        const __half2* h = (const __half2*)&v;
#pragma unroll
        for (int i = 0; i < 4; i++) {
            float2 f = __half22float2(h[i]);
            a[2 * i]     = fmaf(sc, f.x, a[2 * i]);
            a[2 * i + 1] = fmaf(sc, f.y, a[2 * i + 1]);
        }
    };

    const float dv = g_dinv[gw];
    add_row(((const uint4*)(g_gbuf + (size_t)gw * H_DIM))[lane], dv);

    const int beg = g_off[gw];
    const int end = g_off[gw + 1];
    for (int j = beg; j < end; ++j) {
        int src = g_csr[j];
        add_row(((const uint4*)(g_gbuf + (size_t)src * H_DIM))[lane], g_dinv[src]);
    }

    int c = lane * 8;
    float4 bb0 = *(const float4*)&b1[c];
    float4 bb1 = *(const float4*)&b1[c + 4];
    float4 w0  = *(const float4*)&W2[c];
    float4 w1  = *(const float4*)&W2[c + 4];

    float s = 0.0f;
    s += fmaxf(fmaf(dv, a[0], bb0.x), 0.f) * w0.x;
    s += fmaxf(fmaf(dv, a[1], bb0.y), 0.f) * w0.y;
    s += fmaxf(fmaf(dv, a[2], bb0.z), 0.f) * w0.z;
    s += fmaxf(fmaf(dv, a[3], bb0.w), 0.f) * w0.w;
    s += fmaxf(fmaf(dv, a[4], bb1.x), 0.f) * w1.x;
    s += fmaxf(fmaf(dv, a[5], bb1.y), 0.f) * w1.y;
    s += fmaxf(fmaf(dv, a[6], bb1.z), 0.f) * w1.z;
    s += fmaxf(fmaf(dv, a[7], bb1.w), 0.f) * w1.w;

#pragma unroll
    for (int o = 16; o > 0; o >>= 1) s += __shfl_down_sync(0xffffffffu, s, o);
    if (lane == 0) g_t[gw] = dv * s;
}

// ---- layer-2 aggregation ----
__global__ __launch_bounds__(256) void k_agg2(const float* __restrict__ b2,
                                              float* __restrict__ out) {
    int gw   = (blockIdx.x * blockDim.x + threadIdx.x) >> 5;
    int lane = threadIdx.x & 31;
    if (gw >= N_NODES) return;
    const int beg = g_off[gw];
    const int end = g_off[gw + 1];
    float s = (lane == 0) ? g_t[gw] : 0.0f;
    for (int j = beg + lane; j < end; j += 32) s += g_t[g_csr[j]];
#pragma unroll
    for (int o = 16; o > 0; o >>= 1) s += __shfl_down_sync(0xffffffffu, s, o);
    if (lane == 0) out[gw] = fmaf(g_dinv[gw], s, b2[0]);
}

// ---------------- launch ----------------
extern "C" void kernel_launch(void* const* d_in, const int* in_sizes, int n_in,
                              void* d_out, int out_size) {
    const float* x   = (const float*)d_in[0];
    const void*  ei  = d_in[1];
    const float* W1  = (const float*)d_in[2];
    const float* b1  = (const float*)d_in[3];
    const float* W2  = (const float*)d_in[4];
    const float* b2  = (const float*)d_in[5];
    float*       out = (float*)d_out;

    (void)in_sizes; (void)n_in; (void)out_size;

    static int attr_set = 0;
    if (!attr_set) {
        cudaFuncSetAttribute(k_gemm1, cudaFuncAttributeMaxDynamicSharedMemorySize,
                             GEMM_SMEM_BYTES);
        attr_set = 1;
    }

    const int TB = 256;
    const int nb_nodes = (N_NODES + TB - 1) / TB;
    const int nb_edges = (E_EDGES + TB - 1) / TB;
    const int warps_blocks = (N_NODES * 32 + TB - 1) / TB;
    const int xh_blocks = (N_NODES * F_IN_D) / (TB * 8);   // exact: 25000
    dim3 wgrid(F_IN_D / 32, H_DIM / 32);
    dim3 ggrid((N_NODES + 127) / 128, H_DIM / 128);

    if (s_ok) {
        // side stream: convert inputs to fp16, then fp16 tensor-core GEMM
        cudaEventRecord(ev_fork, 0);
        cudaStreamWaitEvent(s_side, ev_fork, 0);
        k_wh<<<wgrid, 1024, 0, s_side>>>(W1);
        k_xh<<<xh_blocks, TB, 0, s_side>>>(x);
        k_gemm1<<<ggrid, 256, GEMM_SMEM_BYTES, s_side>>>();
        cudaEventRecord(ev_join, s_side);

        // main stream: CSR chain, concurrent with the GEMM pipeline
        k_zero_detect<<<nb_nodes, TB>>>((const int*)ei);
        k_prep<<<nb_edges, TB>>>(ei);
        k_scan1<<<SCAN_BLKS, 1024>>>();
        k_scan2<<<1, 128>>>();
        k_scan3<<<nb_nodes, TB>>>();
        k_fill_csr<<<nb_edges, TB>>>();

        cudaStreamWaitEvent(0, ev_join, 0);
    } else {
        k_zero_detect<<<nb_nodes, TB>>>((const int*)ei);
        k_prep<<<nb_edges, TB>>>(ei);
        k_scan1<<<SCAN_BLKS, 1024>>>();
        k_scan2<<<1, 128>>>();
        k_scan3<<<nb_nodes, TB>>>();
        k_fill_csr<<<nb_edges, TB>>>();
        k_wh<<<wgrid, 1024>>>(W1);
        k_xh<<<xh_blocks, TB>>>(x);
        k_gemm1<<<ggrid, 256, GEMM_SMEM_BYTES>>>();
    }

    k_fuse<<<warps_blocks, TB>>>(b1, W2);
    k_agg2<<<warps_blocks, TB>>>(b2, out);
}